// round 7
// baseline (speedup 1.0000x reference)
#include <cuda_runtime.h>
#include <cuda_bf16.h>
#include <cstdint>

// Problem shape (fixed by the dataset)
#define B_ 8
#define T_ 4096
#define F_ 512
#define ROWS_ (B_ * T_)

#define NPROD 148
#define NCONS 148
#define GRID_ (NPROD + NCONS)
#define BLK_  512
#define NGRP  4
#define GRP_ROWS (ROWS_ / NGRP)    // 8192 rows = 2 batches per group

// Scratch (no allocations allowed) — device globals.
__device__ float g_z[ROWS_];          // linear scores (monotone-equiv. for peaks)
__device__ int   g_pos[ROWS_];        // compaction destination per row, -1 if not peak
__device__ int   g_hlens[B_];         // peak counts per batch
__device__ unsigned g_done[NGRP];     // producers finished with group g
__device__ volatile unsigned g_scan_done[B_];  // scan finished for batch b
__device__ unsigned g_finish;         // consumer completion counter (for reset)

__global__ void __launch_bounds__(BLK_, 2)
k_pipe(const float* __restrict__ feat, const float* __restrict__ W,
       float* __restrict__ out, int out_size) {
    const int tid  = threadIdx.x;
    const int lane = tid & 31;
    const int wid  = tid >> 5;               // 0..15
    const int bid  = blockIdx.x;

    __shared__ int warp_sums[16];
    __shared__ int warp_incl[16];

    // ==================================================================
    // PRODUCERS (bids 0..147): GEMV, group by group, never wait.
    // ==================================================================
    if (bid < NPROD) {
        const float4* w4 = reinterpret_cast<const float4*>(W);
        float4 wreg[4];
#pragma unroll
        for (int i = 0; i < 4; i++) wreg[i] = w4[lane + i * 32];

        // warp-major global warp index spreads idle warps across CTAs
        const int gw = wid * NPROD + bid;    // 0..2367

        for (int g = 0; g < NGRP; g++) {
            const int r0 = g * GRP_ROWS + gw * 4;
            if (gw * 4 < GRP_ROWS) {         // 2048 active warps per group
                const float4* f0 = reinterpret_cast<const float4*>(feat + (size_t)(r0 + 0) * F_);
                const float4* f1 = reinterpret_cast<const float4*>(feat + (size_t)(r0 + 1) * F_);
                const float4* f2 = reinterpret_cast<const float4*>(feat + (size_t)(r0 + 2) * F_);
                const float4* f3 = reinterpret_cast<const float4*>(feat + (size_t)(r0 + 3) * F_);
                float s0 = 0.f, s1 = 0.f, s2 = 0.f, s3 = 0.f;
#pragma unroll
                for (int i = 0; i < 4; i++) {
                    const int idx = lane + i * 32;
                    const float4 w = wreg[i];
                    float4 a0 = f0[idx];
                    float4 a1 = f1[idx];
                    float4 a2 = f2[idx];
                    float4 a3 = f3[idx];
                    s0 += a0.x * w.x + a0.y * w.y + a0.z * w.z + a0.w * w.w;
                    s1 += a1.x * w.x + a1.y * w.y + a1.z * w.z + a1.w * w.w;
                    s2 += a2.x * w.x + a2.y * w.y + a2.z * w.z + a2.w * w.w;
                    s3 += a3.x * w.x + a3.y * w.y + a3.z * w.z + a3.w * w.w;
                }
#pragma unroll
                for (int o = 16; o > 0; o >>= 1) {
                    s0 += __shfl_down_sync(0xFFFFFFFFu, s0, o);
                    s1 += __shfl_down_sync(0xFFFFFFFFu, s1, o);
                    s2 += __shfl_down_sync(0xFFFFFFFFu, s2, o);
                    s3 += __shfl_down_sync(0xFFFFFFFFu, s3, o);
                }
                if (lane == 0) {
                    g_z[r0 + 0] = s0;
                    g_z[r0 + 1] = s1;
                    g_z[r0 + 2] = s2;
                    g_z[r0 + 3] = s3;
                }
            }
            __syncthreads();                 // all warps of this CTA done with g
            if (tid == 0) {
                __threadfence();             // publish z before counting
                atomicAdd(&g_done[g], 1u);
            }
        }
        return;                              // producers exit
    }

    // ==================================================================
    // CONSUMERS (bids 148..295): scan (first 8) + compaction, per group.
    // ==================================================================
    const int cid = bid - NPROD;             // 0..147

    for (int g = 0; g < NGRP; g++) {
        // ---- scanner role: consumer cid==b scans batch b (b in {2g, 2g+1})
        if (cid == 2 * g || cid == 2 * g + 1) {
            const int b = cid;
            if (tid == 0) {
                while (atomicAdd(&g_done[g], 0u) < NPROD) __nanosleep(200);
                __threadfence();             // acquire producers' z
            }
            __syncthreads();

            const float* zb = g_z + b * T_;
            const int t0 = tid * 8;          // 512 threads * 8 = 4096
            int flags[8];
            int cnt = 0;
#pragma unroll
            for (int k = 0; k < 8; k++) {
                int t = t0 + k;
                float c = zb[t];
                float l = (t > 0)      ? zb[t - 1] : c;
                float r = (t < T_ - 1) ? zb[t + 1] : c;
                flags[k] = (c >= l) & (c >= r);
                cnt += flags[k];
            }
            int v = cnt;
#pragma unroll
            for (int o = 1; o < 32; o <<= 1) {
                int n = __shfl_up_sync(0xFFFFFFFFu, v, o);
                if (lane >= o) v += n;
            }
            if (lane == 31) warp_sums[wid] = v;
            __syncthreads();
            if (wid == 0 && lane < 16) {
                int s = warp_sums[lane];
#pragma unroll
                for (int o = 1; o < 16; o <<= 1) {
                    int n = __shfl_up_sync(0x0000FFFFu, s, o);
                    if (lane >= o) s += n;
                }
                warp_incl[lane] = s;
            }
            __syncthreads();

            int excl = (v - cnt) + (wid > 0 ? warp_incl[wid - 1] : 0);
#pragma unroll
            for (int k = 0; k < 8; k++) {
                int t = t0 + k;
                g_pos[b * T_ + t] = flags[k] ? excl : -1;
                excl += flags[k];
            }
            if (tid == 0) {
                int hl = warp_incl[15];
                g_hlens[b] = hl;
                if (out_size >= ROWS_ * F_ + B_)
                    out[(size_t)ROWS_ * F_ + b] = (float)hl;
            }
            __syncthreads();
            if (tid == 0) {
                __threadfence();             // publish pos/hlens
                g_scan_done[b] = 1u;
            }
        }

        // ---- all consumers wait for both batch scans of this group
        if (tid == 0) {
            while (g_scan_done[2 * g] == 0u)     __nanosleep(200);
            while (g_scan_done[2 * g + 1] == 0u) __nanosleep(200);
            __threadfence();                 // acquire pos/hlens
        }
        __syncthreads();

        const int hl0 = g_hlens[2 * g];
        const int hl1 = g_hlens[2 * g + 1];

        // ---- compact group g: 4 sub-groups of 128 threads x 4 rows each
        {
            const int sub = tid >> 7;        // 0..3
            const int j   = tid & 127;       // float4 index within row
            const float4 z4 = make_float4(0.f, 0.f, 0.f, 0.f);
            const int gend = (g + 1) * GRP_ROWS;

            for (int base = g * GRP_ROWS + (sub * NCONS + cid) * 4;
                 base < gend; base += NCONS * 16) {
                int p[4], tt[4], bb[4];
#pragma unroll
                for (int k = 0; k < 4; k++) {
                    const int row = base + k;
                    p[k]  = g_pos[row];
                    bb[k] = row >> 12;       // T_ = 4096
                    tt[k] = row & (T_ - 1);
                }
                float4 v4[4];
#pragma unroll
                for (int k = 0; k < 4; k++) {
                    if (p[k] >= 0)
                        v4[k] = reinterpret_cast<const float4*>(feat + (size_t)(base + k) * F_)[j];
                }
#pragma unroll
                for (int k = 0; k < 4; k++) {
                    const int hl = (bb[k] == 2 * g) ? hl0 : hl1;
                    if (p[k] >= 0) {
                        float4* d = reinterpret_cast<float4*>(out + ((size_t)bb[k] * T_ + p[k]) * F_);
                        __stcs(&d[j], v4[k]);
                    }
                    if (tt[k] >= hl) {
                        float4* d = reinterpret_cast<float4*>(out + (size_t)(base + k) * F_);
                        __stcs(&d[j], z4);
                    }
                }
            }
        }
    }

    // ---- reset flags for next (graph-replayed) launch: last consumer CTA
    __syncthreads();
    if (tid == 0) {
        __threadfence();
        unsigned f = atomicAdd(&g_finish, 1u);
        if (f == NCONS - 1) {
#pragma unroll
            for (int i = 0; i < NGRP; i++) g_done[i] = 0u;
#pragma unroll
            for (int i = 0; i < B_; i++) g_scan_done[i] = 0u;
            g_finish = 0u;
            __threadfence();
        }
    }
}

extern "C" void kernel_launch(void* const* d_in, const int* in_sizes, int n_in,
                              void* d_out, int out_size) {
    const float* feat = (const float*)d_in[0];
    const float* W    = (const float*)d_in[1];
    float* out        = (float*)d_out;
    k_pipe<<<GRID_, BLK_>>>(feat, W, out, out_size);
}